// round 10
// baseline (speedup 1.0000x reference)
#include <cuda_runtime.h>
#include <cuda_fp16.h>
#include <cuda_bf16.h>
#include <cstdint>

#define USER_NUM 100000
#define ITEM_NUM 50000
#define N_NODES  (USER_NUM + ITEM_NUM)   // 150000
#define EMB      64
#define TOT      (N_NODES * EMB)         // 9,600,000 elements
#define USER_ELEMS (USER_NUM * EMB)
#define NNZ_MAX  4800000
#define SCAN_CHUNK 1024
#define NCHUNK   ((N_NODES + SCAN_CHUNK - 1) / SCAN_CHUNK)   // 147

// Static device scratch (no runtime allocation allowed)
__device__ __half g_ego[TOT];            // fp16 copy of concat(user,item)
__device__ __half g_h1[TOT];             // layer-1 output (fp16)
__device__ __half g_h2[TOT];             // layer-2 output (fp16)
__device__ int   g_rowptr[N_NODES + 1];
__device__ int   g_cursor[N_NODES];
__device__ int   g_counts[N_NODES];
__device__ __align__(16) int2 g_edges[NNZ_MAX];  // (col, val-bits), row-sorted
__device__ int   g_partial[256];

// ---------------------------------------------------------------------------
// zero the row histogram (tiny, must precede conv_hist)
// ---------------------------------------------------------------------------
__global__ void zero_counts(int* __restrict__ counts) {
    int i = blockIdx.x * blockDim.x + threadIdx.x;
    if (i < N_NODES) counts[i] = 0;
}

// ---------------------------------------------------------------------------
// FUSED: convert ego -> fp16  +  per-row histogram.
// ---------------------------------------------------------------------------
__global__ void conv_hist(const float2* __restrict__ user2,
                          const float2* __restrict__ item2,
                          __half2* __restrict__ ego2,
                          const int* __restrict__ row,
                          int* __restrict__ counts, int nnz) {
    int i = blockIdx.x * blockDim.x + threadIdx.x;
    if (i < TOT / 2) {
        float2 v = (i < USER_ELEMS / 2) ? __ldg(user2 + i)
                                        : __ldg(item2 + (i - USER_ELEMS / 2));
        ego2[i] = __floats2half2_rn(v.x, v.y);
    }
    if (i < nnz) atomicAdd(&counts[__ldcs(row + i)], 1);
}

// ---------------------------------------------------------------------------
// Scan stage 1: per-chunk sums (147 partials)
// ---------------------------------------------------------------------------
__global__ void scan_reduce(const int* __restrict__ counts,
                            int* __restrict__ partial) {
    __shared__ int s[SCAN_CHUNK];
    int i = blockIdx.x * SCAN_CHUNK + threadIdx.x;
    s[threadIdx.x] = (i < N_NODES) ? counts[i] : 0;
    __syncthreads();
    for (int st = SCAN_CHUNK / 2; st > 0; st >>= 1) {
        if (threadIdx.x < st) s[threadIdx.x] += s[threadIdx.x + st];
        __syncthreads();
    }
    if (threadIdx.x == 0) partial[blockIdx.x] = s[0];
}

// ---------------------------------------------------------------------------
// Scan stage 2 (fused): every block redundantly scans the partials in smem,
// then does its chunk's exclusive scan -> rowptr, cursor.
// ---------------------------------------------------------------------------
__global__ void scan_final(const int* __restrict__ counts,
                           const int* __restrict__ partial,
                           int* __restrict__ rowptr,
                           int* __restrict__ cursor, int nnz) {
    __shared__ int sp[256];
    __shared__ int s[SCAN_CHUNK];

    if (threadIdx.x < 256) {
        int v = (threadIdx.x < NCHUNK) ? partial[threadIdx.x] : 0;
        sp[threadIdx.x] = v;
    }
    __syncthreads();
    for (int st = 1; st < 256; st <<= 1) {
        int t = 0;
        if (threadIdx.x < 256 && threadIdx.x >= st) t = sp[threadIdx.x - st];
        __syncthreads();
        if (threadIdx.x < 256) sp[threadIdx.x] += t;
        __syncthreads();
    }
    int block_ex = (blockIdx.x == 0) ? 0 : sp[blockIdx.x - 1];

    int i = blockIdx.x * SCAN_CHUNK + threadIdx.x;
    int v = (i < N_NODES) ? counts[i] : 0;
    s[threadIdx.x] = v;
    __syncthreads();
    for (int st = 1; st < SCAN_CHUNK; st <<= 1) {
        int t = (threadIdx.x >= st) ? s[threadIdx.x - st] : 0;
        __syncthreads();
        s[threadIdx.x] += t;
        __syncthreads();
    }
    if (i < N_NODES) {
        int ex = block_ex + s[threadIdx.x] - v;
        rowptr[i] = ex;
        cursor[i] = ex;
    }
    if (i == 0) rowptr[N_NODES] = nnz;
}

// ---------------------------------------------------------------------------
// Counting-sort stage 3: scatter edges into row-sorted packed array
// ---------------------------------------------------------------------------
__global__ void scatter_kernel(const int* __restrict__ row,
                               const int* __restrict__ col,
                               const float* __restrict__ vals,
                               int* __restrict__ cursor,
                               int2* __restrict__ edges, int nnz) {
    int i = blockIdx.x * blockDim.x + threadIdx.x;
    if (i < nnz) {
        int r = __ldcs(row + i);
        int p = atomicAdd(&cursor[r], 1);
        edges[p] = make_int2(__ldcs(col + i), __float_as_int(__ldcs(vals + i)));
    }
}

// ---------------------------------------------------------------------------
// CSR SpMM, warp per row, HALF-WARP EDGE PAIRING.
// Edges loaded as int4 (2 edges / warp-uniform load). Lanes 0-15 gather edge
// A's fp16 row (8B per lane), lanes 16-31 edge B's — one LDG.64 instruction
// serves 2 edges. LDG instructions/edge: 2 -> 1 (LSU issue floor halved).
// Each lane owns 4 consecutive dims (4*sub .. 4*sub+3) in fp32; half-warps
// combined by shfl_xor(16) at the row tail.
// FINAL=false: y[row] = h (fp16)
// FINAL=true : out[row] = (ego + h1 + h2 + h) * 0.25  (fp32), no y store
// ---------------------------------------------------------------------------
template<bool FINAL>
__global__ void spmm_csr(const int* __restrict__ rowptr,
                         const int2* __restrict__ edges,
                         const __half* __restrict__ x,     // gather source
                         __half* __restrict__ y,           // !FINAL
                         const __half* __restrict__ ego,   // FINAL
                         const __half* __restrict__ h1,    // FINAL
                         float* __restrict__ out) {        // FINAL
    int warp = (blockIdx.x * blockDim.x + threadIdx.x) >> 5;
    int lane = threadIdx.x & 31;
    if (warp >= N_NODES) return;
    int half = lane >> 4;       // 0 or 1
    int sub  = lane & 15;       // position within half-warp

    int start = __ldg(rowptr + warp);
    int end   = __ldg(rowptr + warp + 1);

    float a0 = 0.f, a1 = 0.f, a2 = 0.f, a3 = 0.f;

    // scalar edge (both halves load same row -> broadcast; half 1 masked)
    auto scalar_edge = [&](int ei) {
        int2 ed = __ldg(edges + ei);
        float v = half ? 0.f : __int_as_float(ed.y);
        uint2 r = __ldg(reinterpret_cast<const uint2*>(x + (size_t)ed.x * EMB) + sub);
        float2 f0 = __half22float2(*reinterpret_cast<__half2*>(&r.x));
        float2 f1 = __half22float2(*reinterpret_cast<__half2*>(&r.y));
        a0 = fmaf(v, f0.x, a0); a1 = fmaf(v, f0.y, a1);
        a2 = fmaf(v, f1.x, a2); a3 = fmaf(v, f1.y, a3);
    };

    int e = start;
    if ((e & 1) && e < end) { scalar_edge(e); e++; }     // align to pair

    // 2 pairs (4 edges) per iter: 2 int4 + 2 gather LDGs front-batched (MLP 4)
    for (; e + 4 <= end; e += 4) {
        int4 q0 = __ldg(reinterpret_cast<const int4*>(edges + e));
        int4 q1 = __ldg(reinterpret_cast<const int4*>(edges + e + 2));
        int   c0 = half ? q0.z : q0.x;
        float v0 = __int_as_float(half ? q0.w : q0.y);
        int   c1 = half ? q1.z : q1.x;
        float v1 = __int_as_float(half ? q1.w : q1.y);
        uint2 r0 = __ldg(reinterpret_cast<const uint2*>(x + (size_t)c0 * EMB) + sub);
        uint2 r1 = __ldg(reinterpret_cast<const uint2*>(x + (size_t)c1 * EMB) + sub);
        float2 f00 = __half22float2(*reinterpret_cast<__half2*>(&r0.x));
        float2 f01 = __half22float2(*reinterpret_cast<__half2*>(&r0.y));
        float2 f10 = __half22float2(*reinterpret_cast<__half2*>(&r1.x));
        float2 f11 = __half22float2(*reinterpret_cast<__half2*>(&r1.y));
        a0 = fmaf(v0, f00.x, a0); a1 = fmaf(v0, f00.y, a1);
        a2 = fmaf(v0, f01.x, a2); a3 = fmaf(v0, f01.y, a3);
        a0 = fmaf(v1, f10.x, a0); a1 = fmaf(v1, f10.y, a1);
        a2 = fmaf(v1, f11.x, a2); a3 = fmaf(v1, f11.y, a3);
    }
    // remaining single pair
    if (e + 2 <= end) {
        int4 q0 = __ldg(reinterpret_cast<const int4*>(edges + e));
        int   c0 = half ? q0.z : q0.x;
        float v0 = __int_as_float(half ? q0.w : q0.y);
        uint2 r0 = __ldg(reinterpret_cast<const uint2*>(x + (size_t)c0 * EMB) + sub);
        float2 f00 = __half22float2(*reinterpret_cast<__half2*>(&r0.x));
        float2 f01 = __half22float2(*reinterpret_cast<__half2*>(&r0.y));
        a0 = fmaf(v0, f00.x, a0); a1 = fmaf(v0, f00.y, a1);
        a2 = fmaf(v0, f01.x, a2); a3 = fmaf(v0, f01.y, a3);
        e += 2;
    }
    if (e < end) scalar_edge(e);                          // trailing odd edge

    // combine the two half-warps (both halves end with the full sum)
    a0 += __shfl_xor_sync(0xffffffffu, a0, 16);
    a1 += __shfl_xor_sync(0xffffffffu, a1, 16);
    a2 += __shfl_xor_sync(0xffffffffu, a2, 16);
    a3 += __shfl_xor_sync(0xffffffffu, a3, 16);

    if (!FINAL) {
        if (half == 0) {
            uint2 st;
            __half2 p0 = __floats2half2_rn(a0, a1);
            __half2 p1 = __floats2half2_rn(a2, a3);
            st.x = *reinterpret_cast<uint32_t*>(&p0);
            st.y = *reinterpret_cast<uint32_t*>(&p1);
            reinterpret_cast<uint2*>(y + (size_t)warp * EMB)[sub] = st;
        }
    } else {
        // all lanes load (broadcast within half), half 0 stores float4
        uint2 re = __ldg(reinterpret_cast<const uint2*>(ego + (size_t)warp * EMB) + sub);
        uint2 r1_ = __ldg(reinterpret_cast<const uint2*>(h1  + (size_t)warp * EMB) + sub);
        uint2 r2_ = __ldg(reinterpret_cast<const uint2*>(x   + (size_t)warp * EMB) + sub);
        if (half == 0) {
            float2 e0 = __half22float2(*reinterpret_cast<__half2*>(&re.x));
            float2 e1 = __half22float2(*reinterpret_cast<__half2*>(&re.y));
            float2 b0 = __half22float2(*reinterpret_cast<__half2*>(&r1_.x));
            float2 b1 = __half22float2(*reinterpret_cast<__half2*>(&r1_.y));
            float2 c0 = __half22float2(*reinterpret_cast<__half2*>(&r2_.x));
            float2 c1 = __half22float2(*reinterpret_cast<__half2*>(&r2_.y));
            float4 o;
            o.x = (e0.x + b0.x + c0.x + a0) * 0.25f;
            o.y = (e0.y + b0.y + c0.y + a1) * 0.25f;
            o.z = (e1.x + b1.x + c1.x + a2) * 0.25f;
            o.w = (e1.y + b1.y + c1.y + a3) * 0.25f;
            reinterpret_cast<float4*>(out + (size_t)warp * EMB)[sub] = o;
        }
    }
}

extern "C" void kernel_launch(void* const* d_in, const int* in_sizes, int n_in,
                              void* d_out, int out_size) {
    const float* user_emb = (const float*)d_in[0];
    const float* item_emb = (const float*)d_in[1];
    const int*   adj_row  = (const int*)  d_in[2];
    const int*   adj_col  = (const int*)  d_in[3];
    const float* adj_vals = (const float*)d_in[4];
    float* out = (float*)d_out;
    int nnz = in_sizes[2];

    __half* ego;   cudaGetSymbolAddress((void**)&ego,    g_ego);
    __half* h1;    cudaGetSymbolAddress((void**)&h1,     g_h1);
    __half* h2;    cudaGetSymbolAddress((void**)&h2,     g_h2);
    int*   rowptr; cudaGetSymbolAddress((void**)&rowptr, g_rowptr);
    int*   cursor; cudaGetSymbolAddress((void**)&cursor, g_cursor);
    int*   counts; cudaGetSymbolAddress((void**)&counts, g_counts);
    int2*  edges;  cudaGetSymbolAddress((void**)&edges,  g_edges);
    int*   partial;cudaGetSymbolAddress((void**)&partial,g_partial);

    const int T = 256;
    const int ZC_BLOCKS = (N_NODES + T - 1) / T;
    const int CH_BLOCKS = ((TOT / 2 > nnz ? TOT / 2 : nnz) + T - 1) / T;
    const int EG_BLOCKS = (nnz + T - 1) / T;
    const int SP_BLOCKS = (N_NODES * 32 + T - 1) / T;    // warp per row

    zero_counts<<<ZC_BLOCKS, T>>>(counts);
    conv_hist<<<CH_BLOCKS, T>>>((const float2*)user_emb, (const float2*)item_emb,
                                (__half2*)ego, adj_row, counts, nnz);
    scan_reduce<<<NCHUNK, SCAN_CHUNK>>>(counts, partial);
    scan_final<<<NCHUNK, SCAN_CHUNK>>>(counts, partial, rowptr, cursor, nnz);
    scatter_kernel<<<EG_BLOCKS, T>>>(adj_row, adj_col, adj_vals, cursor, edges, nnz);

    // layer 1: h1 = A*ego
    spmm_csr<false><<<SP_BLOCKS, T>>>(rowptr, edges, ego, h1, nullptr, nullptr, nullptr);
    // layer 2: h2 = A*h1
    spmm_csr<false><<<SP_BLOCKS, T>>>(rowptr, edges, h1, h2, nullptr, nullptr, nullptr);
    // layer 3: out = (ego + h1 + h2 + A*h2) / 4
    spmm_csr<true><<<SP_BLOCKS, T>>>(rowptr, edges, h2, nullptr, ego, h1, out);
}